// round 7
// baseline (speedup 1.0000x reference)
#include <cuda_runtime.h>
#include <cuda_bf16.h>
#include <stdint.h>

#define B_DIM 2048
#define D_DIM 128
#define C_DIM 100000
#define KNN 10
#define TILE 128
#define NT 782   /* ceil(100000/128) column tiles */
#define MT 16    /* 2048/128 row tiles */

// Scratch (device globals: allocation-free per harness rules)
__device__ __align__(16) __nv_bfloat16 g_enc_bf16[B_DIM * D_DIM];
__device__ float g_enc_norm[B_DIM];
__device__ __align__(16) __nv_bfloat16 g_mem_bf16[C_DIM * D_DIM];
__device__ float g_mem_norm[C_DIM];
__device__ __align__(16) float g_part[(size_t)B_DIM * NT * KNN];  // 64 MB partials

// ---------------------------------------------------------------------------
__device__ __forceinline__ uint32_t smem_u32(const void* p) {
    uint32_t a;
    asm("{ .reg .u64 t; cvta.to.shared.u64 t, %1; cvt.u32.u64 %0, t; }" : "=r"(a) : "l"(p));
    return a;
}
__device__ __forceinline__ void ldsm_x4(uint32_t* r, uint32_t addr) {
    asm volatile("ldmatrix.sync.aligned.m8n8.x4.shared.b16 {%0,%1,%2,%3}, [%4];"
                 : "=r"(r[0]), "=r"(r[1]), "=r"(r[2]), "=r"(r[3]) : "r"(addr));
}
__device__ __forceinline__ void cp16(uint32_t dst, const void* src) {
    asm volatile("cp.async.cg.shared.global [%0], [%1], 16;" :: "r"(dst), "l"(src));
}
__device__ __forceinline__ void cp16z(uint32_t dst, const void* src, int srcsize) {
    asm volatile("cp.async.cg.shared.global [%0], [%1], 16, %2;"
                 :: "r"(dst), "l"(src), "r"(srcsize));
}

// ---------------------------------------------------------------------------
// Kernel 1: fused 2-layer encoder (one CTA per batch row).
// ---------------------------------------------------------------------------
__global__ void encoder_kernel(const float* __restrict__ state,
                               const float* __restrict__ W1, const float* __restrict__ b1,
                               const float* __restrict__ W2, const float* __restrict__ b2) {
    __shared__ float s_in[D_DIM];
    __shared__ float s_h[D_DIM];
    __shared__ float s_red[D_DIM];
    const int b = blockIdx.x;
    const int j = threadIdx.x;

    s_in[j] = state[b * D_DIM + j];
    __syncthreads();

    float acc = b1[j];
#pragma unroll 8
    for (int k = 0; k < D_DIM; k++) acc = fmaf(s_in[k], W1[k * D_DIM + j], acc);
    s_h[j] = fmaxf(acc, 0.0f);
    __syncthreads();

    float acc2 = b2[j];
#pragma unroll 8
    for (int k = 0; k < D_DIM; k++) acc2 = fmaf(s_h[k], W2[k * D_DIM + j], acc2);

    __nv_bfloat16 q = __float2bfloat16(acc2);
    float qf = __bfloat162float(q);
    g_enc_bf16[b * D_DIM + j] = q;
    s_red[j] = qf * qf;
    __syncthreads();
#pragma unroll
    for (int s = 64; s > 0; s >>= 1) {
        if (j < s) s_red[j] += s_red[j + s];
        __syncthreads();
    }
    if (j == 0) g_enc_norm[b] = s_red[0];
}

// ---------------------------------------------------------------------------
// Kernel 2: memory -> bf16 + squared norms. One warp per memory row.
// ---------------------------------------------------------------------------
__global__ void memprep_kernel(const float* __restrict__ memory) {
    const int warp = blockIdx.x * (blockDim.x >> 5) + (threadIdx.x >> 5);
    const int lane = threadIdx.x & 31;
    if (warp >= C_DIM) return;

    const float4 v = ((const float4*)(memory + (size_t)warp * D_DIM))[lane];
    __nv_bfloat16 q0 = __float2bfloat16(v.x);
    __nv_bfloat16 q1 = __float2bfloat16(v.y);
    __nv_bfloat16 q2 = __float2bfloat16(v.z);
    __nv_bfloat16 q3 = __float2bfloat16(v.w);
    float f0 = __bfloat162float(q0), f1 = __bfloat162float(q1);
    float f2 = __bfloat162float(q2), f3 = __bfloat162float(q3);

    __nv_bfloat162* dst = (__nv_bfloat162*)(g_mem_bf16 + (size_t)warp * D_DIM);
    dst[lane * 2 + 0] = __halves2bfloat162(q0, q1);
    dst[lane * 2 + 1] = __halves2bfloat162(q2, q3);

    float sum = f0 * f0 + f1 * f1 + f2 * f2 + f3 * f3;
#pragma unroll
    for (int off = 16; off > 0; off >>= 1)
        sum += __shfl_xor_sync(0xFFFFFFFFu, sum, off);
    if (lane == 0) g_mem_norm[warp] = sum;
}

// ---------------------------------------------------------------------------
__device__ __forceinline__ void topk_insert(float (&top)[KNN], float v) {
    if (v < top[KNN - 1]) {
        top[KNN - 1] = v;
#pragma unroll
        for (int i = KNN - 2; i >= 0; i--) {
            if (top[i + 1] < top[i]) {
                float tmp = top[i]; top[i] = top[i + 1]; top[i + 1] = tmp;
            }
        }
    }
}
// Merge partner's sorted top-K via shfl.bfly into own list.
__device__ __forceinline__ void bfly_merge(float (&top)[KNN], int off) {
    float recv[KNN];
#pragma unroll
    for (int i = 0; i < KNN; i++) recv[i] = __shfl_xor_sync(0xFFFFFFFFu, top[i], off);
#pragma unroll
    for (int i = 0; i < KNN; i++) topk_insert(top, recv[i]);
}

// ---------------------------------------------------------------------------
// Kernel 3: distance GEMM (mma.sync bf16) + register-only top-10 epilogue.
// 128x128x128 tile. 8 warps along M: warp w owns rows w*16..w*16+15, all
// 128 cols. Each row's 128 cols live in one lane-quad -> top-10 via 2 bfly
// merges, no epilogue smem, single __syncthreads in the whole kernel.
// Smem swizzle per operand: (row, seg16B) -> unit row*16 + (seg ^ (row&7)).
// ---------------------------------------------------------------------------
__global__ void __launch_bounds__(256, 2) dist_gemm_kernel() {
    extern __shared__ __align__(1024) char smem[];
    const uint32_t sA = smem_u32(smem);
    const uint32_t sB = sA + 32768;
    float* s_norm = (float*)(smem + 65536);   // 128 floats

    const int tid = threadIdx.x;
    const int w = tid >> 5, lane = tid & 31;
    const int g = lane >> 2, t = lane & 3;
    const int m7 = lane & 7;
    const int rowBase = blockIdx.y * TILE;
    const int colBase = blockIdx.x * TILE;

    // stage memory norms for this column tile
    if (tid < 128) {
        int c = colBase + tid;
        s_norm[tid] = (c < C_DIM) ? g_mem_norm[c] : 3.0e38f;
    }

    // ---- stage A and B tiles (full K=128) via cp.async ----
#pragma unroll
    for (int i = 0; i < 8; i++) {
        int idx = tid + i * 256;
        int row = idx >> 4, s = idx & 15;
        uint32_t dst = sA + ((row * 16 + (s ^ (row & 7))) << 4);
        cp16(dst, g_enc_bf16 + (size_t)(rowBase + row) * D_DIM + s * 8);
    }
#pragma unroll
    for (int i = 0; i < 8; i++) {
        int idx = tid + i * 256;
        int row = idx >> 4, s = idx & 15;
        uint32_t dst = sB + ((row * 16 + (s ^ (row & 7))) << 4);
        int col = colBase + row;
        int ccol = (col < C_DIM) ? col : (C_DIM - 1);
        cp16z(dst, g_mem_bf16 + (size_t)ccol * D_DIM + s * 8, (col < C_DIM) ? 16 : 0);
    }
    asm volatile("cp.async.commit_group;");
    asm volatile("cp.async.wait_group 0;" ::: "memory");
    __syncthreads();

    // ---- fragment addressing ----
    const int asel = lane >> 4;          // 0/1: k-seg select for A
    const int bsel = (lane >> 3) & 1;    // 0/1: k-seg select for B
    const uint32_t aoff = sA + ((w * 16 + (lane & 15)) << 8);
    uint32_t boff[8];
#pragma unroll
    for (int p = 0; p < 8; p++)
        boff[p] = sB + ((p * 16 + m7 + ((lane >> 4) & 1) * 8) << 8);

    float acc[16][4];
#pragma unroll
    for (int nj = 0; nj < 16; nj++)
#pragma unroll
        for (int r = 0; r < 4; r++) acc[nj][r] = 0.0f;

    // ---- mainloop: 8 k-steps of m16n8k16, 16 MMAs per warp per step ----
#pragma unroll
    for (int ks = 0; ks < 8; ks++) {
        const uint32_t sa = (uint32_t)(((2 * ks + asel) ^ m7) << 4);
        const uint32_t sb = (uint32_t)(((2 * ks + bsel) ^ m7) << 4);
        uint32_t a[4];
        ldsm_x4(a, aoff + sa);
#pragma unroll
        for (int p = 0; p < 8; p++) {
            uint32_t b[4];
            ldsm_x4(b, boff[p] + sb);
#pragma unroll
            for (int h = 0; h < 2; h++) {   // nj = 2p+h
                asm volatile(
                    "mma.sync.aligned.m16n8k16.row.col.f32.bf16.bf16.f32 "
                    "{%0,%1,%2,%3}, {%4,%5,%6,%7}, {%8,%9}, {%0,%1,%2,%3};\n"
                    : "+f"(acc[2 * p + h][0]), "+f"(acc[2 * p + h][1]),
                      "+f"(acc[2 * p + h][2]), "+f"(acc[2 * p + h][3])
                    : "r"(a[0]), "r"(a[1]), "r"(a[2]), "r"(a[3]),
                      "r"(b[2 * h]), "r"(b[2 * h + 1]));
            }
        }
    }

    // ---- epilogue: register top-10 per row, quad bfly merge ----
    const int row0 = rowBase + w * 16 + g;      // rows row0, row0+8
    const float en0 = g_enc_norm[row0];
    const float en1 = g_enc_norm[row0 + 8];

    float topA[KNN], topB[KNN];
#pragma unroll
    for (int i = 0; i < KNN; i++) { topA[i] = 3.0e38f; topB[i] = 3.0e38f; }

#pragma unroll
    for (int nj = 0; nj < 16; nj++) {
        const int cb = nj * 8 + 2 * t;
        const float mn0 = s_norm[cb];
        const float mn1 = s_norm[cb + 1];
        topk_insert(topA, en0 + mn0 - 2.0f * acc[nj][0]);
        topk_insert(topA, en0 + mn1 - 2.0f * acc[nj][1]);
        topk_insert(topB, en1 + mn0 - 2.0f * acc[nj][2]);
        topk_insert(topB, en1 + mn1 - 2.0f * acc[nj][3]);
    }
    // quad lanes 4g..4g+3: bfly off 1,2 -> all quad lanes hold row top-10
    bfly_merge(topA, 1); bfly_merge(topA, 2);
    bfly_merge(topB, 1); bfly_merge(topB, 2);

    if (t == 0) {
        float* dst = g_part + ((size_t)row0 * NT + blockIdx.x) * KNN;
#pragma unroll
        for (int i = 0; i < KNN; i++) dst[i] = topA[i];
    } else if (t == 1) {
        float* dst = g_part + ((size_t)(row0 + 8) * NT + blockIdx.x) * KNN;
#pragma unroll
        for (int i = 0; i < KNN; i++) dst[i] = topB[i];
    }
}

// ---------------------------------------------------------------------------
// Kernel 4: merge NT per-tile top-10 lists per row.  NT*KNN = 7820 = 4*1955.
// Per-thread top-10 -> 5 bfly rounds in-warp -> 8 warp lists -> 3 bfly
// rounds in warp 0 -> mean(sqrt(top10)).
// ---------------------------------------------------------------------------
__global__ void reduce_topk(float* __restrict__ out) {
    __shared__ float swarp[8 * KNN];
    const int row = blockIdx.x;
    const int tid = threadIdx.x;
    const int wid = tid >> 5, lane = tid & 31;
    const float4* p4 = (const float4*)(g_part + (size_t)row * NT * KNN);

    float top[KNN];
#pragma unroll
    for (int i = 0; i < KNN; i++) top[i] = 3.0e38f;

    for (int c = tid; c < 1955; c += 256) {
        float4 v = p4[c];
        topk_insert(top, v.x);
        topk_insert(top, v.y);
        topk_insert(top, v.z);
        topk_insert(top, v.w);
    }

#pragma unroll
    for (int off = 16; off > 0; off >>= 1) bfly_merge(top, off);

    if (lane == 0) {
#pragma unroll
        for (int i = 0; i < KNN; i++) swarp[wid * KNN + i] = top[i];
    }
    __syncthreads();

    if (wid == 0) {
        float t2[KNN];
#pragma unroll
        for (int i = 0; i < KNN; i++)
            t2[i] = (lane < 8) ? swarp[lane * KNN + i] : 3.0e38f;
        bfly_merge(t2, 4); bfly_merge(t2, 2); bfly_merge(t2, 1);
        if (lane == 0) {
            float sum = 0.0f;
#pragma unroll
            for (int i = 0; i < KNN; i++) sum += sqrtf(fmaxf(t2[i], 1e-12f));
            out[row] = sum * (1.0f / KNN);
        }
    }
}

// ---------------------------------------------------------------------------
#define SMEM_SZ (65536 + 512)

extern "C" void kernel_launch(void* const* d_in, const int* in_sizes, int n_in,
                              void* d_out, int out_size) {
    const float* state  = (const float*)d_in[0];
    const float* W1     = (const float*)d_in[1];
    const float* b1     = (const float*)d_in[2];
    const float* W2     = (const float*)d_in[3];
    const float* b2     = (const float*)d_in[4];
    const float* memory = (const float*)d_in[5];

    cudaFuncSetAttribute(dist_gemm_kernel,
                         cudaFuncAttributeMaxDynamicSharedMemorySize, SMEM_SZ);

    encoder_kernel<<<B_DIM, 128>>>(state, W1, b1, W2, b2);
    memprep_kernel<<<(C_DIM + 7) / 8, 256>>>(memory);

    dim3 grid(NT, MT);
    dist_gemm_kernel<<<grid, 256, SMEM_SZ>>>();

    reduce_topk<<<B_DIM, 256>>>((float*)d_out);
}

// round 9
// speedup vs baseline: 1.7234x; 1.7234x over previous
#include <cuda_runtime.h>
#include <cuda_bf16.h>
#include <stdint.h>

#define B_DIM 2048
#define D_DIM 128
#define C_DIM 100000
#define KNN 10
#define TILE 128
#define SPAD 132
#define NT 782   /* ceil(100000/128) column tiles */
#define MT 16    /* 2048/128 row tiles */
#define CH 32768 /* smem stride between K-chunks (A+B pair) */

// Scratch (device globals: allocation-free per harness rules)
__device__ __align__(16) __nv_bfloat16 g_enc_bf16[B_DIM * D_DIM];
__device__ float g_enc_norm[B_DIM];
__device__ __align__(16) __nv_bfloat16 g_mem_bf16[C_DIM * D_DIM];
__device__ float g_mem_norm[C_DIM];
__device__ __align__(16) float g_part[(size_t)B_DIM * NT * KNN];  // 64 MB partials

// ---------------------------------------------------------------------------
__device__ __forceinline__ uint32_t smem_u32(const void* p) {
    uint32_t a;
    asm("{ .reg .u64 t; cvta.to.shared.u64 t, %1; cvt.u32.u64 %0, t; }" : "=r"(a) : "l"(p));
    return a;
}
__device__ __forceinline__ void ldsm_x4(uint32_t* r, uint32_t addr) {
    asm volatile("ldmatrix.sync.aligned.m8n8.x4.shared.b16 {%0,%1,%2,%3}, [%4];"
                 : "=r"(r[0]), "=r"(r[1]), "=r"(r[2]), "=r"(r[3]) : "r"(addr));
}
__device__ __forceinline__ void cp16(uint32_t dst, const void* src) {
    asm volatile("cp.async.cg.shared.global [%0], [%1], 16;" :: "r"(dst), "l"(src));
}
__device__ __forceinline__ void cp16z(uint32_t dst, const void* src, int srcsize) {
    asm volatile("cp.async.cg.shared.global [%0], [%1], 16, %2;"
                 :: "r"(dst), "l"(src), "r"(srcsize));
}

// ---------------------------------------------------------------------------
// Kernel 1: fused 2-layer encoder (one CTA per batch row).
// ---------------------------------------------------------------------------
__global__ void encoder_kernel(const float* __restrict__ state,
                               const float* __restrict__ W1, const float* __restrict__ b1,
                               const float* __restrict__ W2, const float* __restrict__ b2) {
    __shared__ float s_in[D_DIM];
    __shared__ float s_h[D_DIM];
    __shared__ float s_red[D_DIM];
    const int b = blockIdx.x;
    const int j = threadIdx.x;

    s_in[j] = state[b * D_DIM + j];
    __syncthreads();

    float acc = b1[j];
#pragma unroll 8
    for (int k = 0; k < D_DIM; k++) acc = fmaf(s_in[k], W1[k * D_DIM + j], acc);
    s_h[j] = fmaxf(acc, 0.0f);
    __syncthreads();

    float acc2 = b2[j];
#pragma unroll 8
    for (int k = 0; k < D_DIM; k++) acc2 = fmaf(s_h[k], W2[k * D_DIM + j], acc2);

    __nv_bfloat16 q = __float2bfloat16(acc2);
    float qf = __bfloat162float(q);
    g_enc_bf16[b * D_DIM + j] = q;
    s_red[j] = qf * qf;
    __syncthreads();
#pragma unroll
    for (int s = 64; s > 0; s >>= 1) {
        if (j < s) s_red[j] += s_red[j + s];
        __syncthreads();
    }
    if (j == 0) g_enc_norm[b] = s_red[0];
}

// ---------------------------------------------------------------------------
// Kernel 2: memory -> bf16 + squared norms. One warp per memory row.
// ---------------------------------------------------------------------------
__global__ void memprep_kernel(const float* __restrict__ memory) {
    const int warp = blockIdx.x * (blockDim.x >> 5) + (threadIdx.x >> 5);
    const int lane = threadIdx.x & 31;
    if (warp >= C_DIM) return;

    const float4 v = ((const float4*)(memory + (size_t)warp * D_DIM))[lane];
    __nv_bfloat16 q0 = __float2bfloat16(v.x);
    __nv_bfloat16 q1 = __float2bfloat16(v.y);
    __nv_bfloat16 q2 = __float2bfloat16(v.z);
    __nv_bfloat16 q3 = __float2bfloat16(v.w);
    float f0 = __bfloat162float(q0), f1 = __bfloat162float(q1);
    float f2 = __bfloat162float(q2), f3 = __bfloat162float(q3);

    __nv_bfloat162* dst = (__nv_bfloat162*)(g_mem_bf16 + (size_t)warp * D_DIM);
    dst[lane * 2 + 0] = __halves2bfloat162(q0, q1);
    dst[lane * 2 + 1] = __halves2bfloat162(q2, q3);

    float sum = f0 * f0 + f1 * f1 + f2 * f2 + f3 * f3;
#pragma unroll
    for (int off = 16; off > 0; off >>= 1)
        sum += __shfl_xor_sync(0xFFFFFFFFu, sum, off);
    if (lane == 0) g_mem_norm[warp] = sum;
}

// ---------------------------------------------------------------------------
__device__ __forceinline__ void topk_insert(float (&top)[KNN], float v) {
    if (v < top[KNN - 1]) {
        top[KNN - 1] = v;
#pragma unroll
        for (int i = KNN - 2; i >= 0; i--) {
            if (top[i + 1] < top[i]) {
                float tmp = top[i]; top[i] = top[i + 1]; top[i + 1] = tmp;
            }
        }
    }
}

// ---------------------------------------------------------------------------
// Kernel 3: distance GEMM (mma.sync bf16) + fused per-tile top-10.
// 128x128x128 tile, 8 warps (4 M x 2 N). K split into two 64-chunks,
// double-buffered cp.async: chunk1 loads overlap chunk0 compute.
// Smem per chunk: A (128x64 bf16, 16KB) + B (16KB); swizzle
// (row, seg16B) -> unit row*8 + (seg ^ (row&7)); 128B row stride.
// Epilogue: sq tile -> smem fp32 (repurposed), 2 thr/row top-10 (R4-proven).
// ---------------------------------------------------------------------------
__global__ void __launch_bounds__(256) dist_gemm_kernel() {
    extern __shared__ __align__(1024) char smem[];
    const uint32_t sA = smem_u32(smem);            // chunk c at sA + c*CH
    const uint32_t sB = sA + 16384;                // chunk c at sB + c*CH
    float* s_tile = (float*)smem;

    const int tid = threadIdx.x;
    const int wid = tid >> 5, lane = tid & 31;
    const int g = lane >> 2, t = lane & 3;
    const int m7 = lane & 7;
    const int wm = wid >> 1, wn = wid & 1;
    const int rowBase = blockIdx.y * TILE;
    const int colBase = blockIdx.x * TILE;

    // ---- stage both K-chunks, one commit group per chunk ----
#pragma unroll
    for (int c = 0; c < 2; c++) {
#pragma unroll
        for (int i = 0; i < 4; i++) {
            int idx = tid + i * 256;               // 1024 16B units
            int row = idx >> 3, s = idx & 7;
            uint32_t dst = sA + c * CH + ((row * 8 + (s ^ (row & 7))) << 4);
            cp16(dst, g_enc_bf16 + (size_t)(rowBase + row) * D_DIM + c * 64 + s * 8);
        }
#pragma unroll
        for (int i = 0; i < 4; i++) {
            int idx = tid + i * 256;
            int row = idx >> 3, s = idx & 7;
            int col = colBase + row;
            int ccol = (col < C_DIM) ? col : (C_DIM - 1);
            uint32_t dst = sB + c * CH + ((row * 8 + (s ^ (row & 7))) << 4);
            cp16z(dst, g_mem_bf16 + (size_t)ccol * D_DIM + c * 64 + s * 8,
                  (col < C_DIM) ? 16 : 0);
        }
        asm volatile("cp.async.commit_group;");
    }

    // ---- fragment lane mapping (per-chunk bases add c*CH) ----
    const int asel = lane >> 4;          // 0/1: k-seg select for A
    const int bsel = (lane >> 3) & 1;    // 0/1: k-seg select for B
    const uint32_t aoff0 = sA + ((wm * 32 + (lane & 15)) << 7);
    const uint32_t aoff1 = aoff0 + (16 << 7);
    uint32_t boff[4];
#pragma unroll
    for (int p = 0; p < 4; p++)
        boff[p] = sB + ((wn * 64 + p * 16 + m7 + ((lane >> 4) & 1) * 8) << 7);

    float acc[2][8][4];
#pragma unroll
    for (int mi = 0; mi < 2; mi++)
#pragma unroll
        for (int nj = 0; nj < 8; nj++)
#pragma unroll
            for (int r = 0; r < 4; r++) acc[mi][nj][r] = 0.0f;

    // ---- pipelined mainloop: chunk0 compute overlaps chunk1 loads ----
#pragma unroll
    for (int c = 0; c < 2; c++) {
        if (c == 0) asm volatile("cp.async.wait_group 1;" ::: "memory");
        else        asm volatile("cp.async.wait_group 0;" ::: "memory");
        __syncthreads();

        const uint32_t co = c * CH;
#pragma unroll
        for (int ks = 0; ks < 4; ks++) {
            const uint32_t sa = (uint32_t)(((2 * ks + asel) ^ m7) << 4);
            const uint32_t sb = (uint32_t)(((2 * ks + bsel) ^ m7) << 4);
            uint32_t a0[4], a1[4];
            ldsm_x4(a0, aoff0 + co + sa);
            ldsm_x4(a1, aoff1 + co + sa);
#pragma unroll
            for (int p = 0; p < 4; p++) {
                uint32_t b[4];
                ldsm_x4(b, boff[p] + co + sb);
#pragma unroll
                for (int h = 0; h < 2; h++) {   // nj = 2p+h
                    asm volatile(
                        "mma.sync.aligned.m16n8k16.row.col.f32.bf16.bf16.f32 "
                        "{%0,%1,%2,%3}, {%4,%5,%6,%7}, {%8,%9}, {%0,%1,%2,%3};\n"
                        : "+f"(acc[0][2 * p + h][0]), "+f"(acc[0][2 * p + h][1]),
                          "+f"(acc[0][2 * p + h][2]), "+f"(acc[0][2 * p + h][3])
                        : "r"(a0[0]), "r"(a0[1]), "r"(a0[2]), "r"(a0[3]),
                          "r"(b[2 * h]), "r"(b[2 * h + 1]));
                    asm volatile(
                        "mma.sync.aligned.m16n8k16.row.col.f32.bf16.bf16.f32 "
                        "{%0,%1,%2,%3}, {%4,%5,%6,%7}, {%8,%9}, {%0,%1,%2,%3};\n"
                        : "+f"(acc[1][2 * p + h][0]), "+f"(acc[1][2 * p + h][1]),
                          "+f"(acc[1][2 * p + h][2]), "+f"(acc[1][2 * p + h][3])
                        : "r"(a1[0]), "r"(a1[1]), "r"(a1[2]), "r"(a1[3]),
                          "r"(b[2 * h]), "r"(b[2 * h + 1]));
                }
            }
        }
    }

    // ---- epilogue: sq tile -> shared fp32 (R4-proven) ----
    __syncthreads();   // all smem operand reads done; safe to repurpose
#pragma unroll
    for (int mi = 0; mi < 2; mi++) {
        const int r0 = wm * 32 + mi * 16 + g;
        const float en0 = g_enc_norm[rowBase + r0];
        const float en8 = g_enc_norm[rowBase + r0 + 8];
#pragma unroll
        for (int nj = 0; nj < 8; nj++) {
            const int cl = wn * 64 + nj * 8 + 2 * t;
            const int col = colBase + cl;
            float2 v0, v1;
            if (col < C_DIM) {   // C_DIM even: pair never straddles the edge
                const float mn0 = g_mem_norm[col];
                const float mn1 = g_mem_norm[col + 1];
                v0.x = en0 + mn0 - 2.0f * acc[mi][nj][0];
                v0.y = en0 + mn1 - 2.0f * acc[mi][nj][1];
                v1.x = en8 + mn0 - 2.0f * acc[mi][nj][2];
                v1.y = en8 + mn1 - 2.0f * acc[mi][nj][3];
            } else {
                v0.x = v0.y = v1.x = v1.y = 3.0e38f;
            }
            *(float2*)(s_tile + (size_t)r0 * SPAD + cl) = v0;
            *(float2*)(s_tile + (size_t)(r0 + 8) * SPAD + cl) = v1;
        }
    }
    __syncthreads();

    // ---- per-row top-10: 2 threads/row, 64 cols each ----
    const int srow = tid >> 1, shalf = tid & 1;
    float top[KNN];
#pragma unroll
    for (int i = 0; i < KNN; i++) top[i] = 3.0e38f;
    const float* bp = s_tile + (size_t)srow * SPAD + shalf * 64;
#pragma unroll 8
    for (int j = 0; j < 64; j++) topk_insert(top, bp[j]);
    __syncthreads();

    if (shalf) {
#pragma unroll
        for (int i = 0; i < KNN; i++) s_tile[srow * KNN + i] = top[i];
    }
    __syncthreads();
    if (!shalf) {
        const float* q = s_tile + srow * KNN;
#pragma unroll
        for (int i = 0; i < KNN; i++) topk_insert(top, q[i]);
        float* dst = g_part + ((size_t)(rowBase + srow) * NT + blockIdx.x) * KNN;
#pragma unroll
        for (int i = 0; i < KNN; i++) dst[i] = top[i];
    }
}

// ---------------------------------------------------------------------------
// Kernel 4: merge NT per-tile top-10 lists per row (float4 loads).
// NT*KNN = 7820 = 4 * 1955.   (R4-proven serial merge tails.)
// ---------------------------------------------------------------------------
__global__ void reduce_topk(float* __restrict__ out) {
    __shared__ float svals[256 * KNN];
    __shared__ float swarp[32 * KNN];
    const int row = blockIdx.x;
    const int tid = threadIdx.x;
    const float4* p4 = (const float4*)(g_part + (size_t)row * NT * KNN);

    float top[KNN];
#pragma unroll
    for (int i = 0; i < KNN; i++) top[i] = 3.0e38f;

    for (int c = tid; c < 1955; c += 256) {
        float4 v = p4[c];
        topk_insert(top, v.x);
        topk_insert(top, v.y);
        topk_insert(top, v.z);
        topk_insert(top, v.w);
    }

#pragma unroll
    for (int i = 0; i < KNN; i++) svals[tid * KNN + i] = top[i];
    __syncthreads();

    if (tid < 32) {
        float t2[KNN];
#pragma unroll
        for (int i = 0; i < KNN; i++) t2[i] = 3.0e38f;
        const int base = tid * 80;
        for (int c = 0; c < 80; c++) topk_insert(t2, svals[base + c]);
#pragma unroll
        for (int i = 0; i < KNN; i++) swarp[tid * KNN + i] = t2[i];
    }
    __syncthreads();

    if (tid == 0) {
        float t3[KNN];
#pragma unroll
        for (int i = 0; i < KNN; i++) t3[i] = 3.0e38f;
        for (int c = 0; c < 32 * KNN; c++) topk_insert(t3, swarp[c]);
        float sum = 0.0f;
#pragma unroll
        for (int i = 0; i < KNN; i++) sum += sqrtf(fmaxf(t3[i], 1e-12f));
        out[row] = sum * (1.0f / KNN);
    }
}

// ---------------------------------------------------------------------------
#define SMEM_SZ (TILE * SPAD * 4)   /* 67584 >= 65536 operand bytes */

extern "C" void kernel_launch(void* const* d_in, const int* in_sizes, int n_in,
                              void* d_out, int out_size) {
    const float* state  = (const float*)d_in[0];
    const float* W1     = (const float*)d_in[1];
    const float* b1     = (const float*)d_in[2];
    const float* W2     = (const float*)d_in[3];
    const float* b2     = (const float*)d_in[4];
    const float* memory = (const float*)d_in[5];

    cudaFuncSetAttribute(dist_gemm_kernel,
                         cudaFuncAttributeMaxDynamicSharedMemorySize, SMEM_SZ);

    encoder_kernel<<<B_DIM, 128>>>(state, W1, b1, W2, b2);
    memprep_kernel<<<(C_DIM + 7) / 8, 256>>>(memory);

    dim3 grid(NT, MT);
    dist_gemm_kernel<<<grid, 256, SMEM_SZ>>>();

    reduce_topk<<<B_DIM, 256>>>((float*)d_out);
}

// round 14
// speedup vs baseline: 1.8255x; 1.0592x over previous
#include <cuda_runtime.h>
#include <cuda_bf16.h>
#include <stdint.h>

#define B_DIM 2048
#define D_DIM 128
#define C_DIM 100000
#define KNN 10
#define TILE 128
#define SPAD 132
#define NT 782   /* ceil(100000/128) column tiles */
#define MT 16    /* 2048/128 row tiles */
#define CH 32768 /* smem stride between K-chunks (A+B pair) */
#define ENC_BLKS 1024          /* 2 batch rows per block */
#define MEM_BLKS 12500         /* 8 memory rows per block */

// Scratch (device globals: allocation-free per harness rules)
__device__ __align__(16) __nv_bfloat16 g_enc_bf16[B_DIM * D_DIM];
__device__ float g_enc_norm[B_DIM];
__device__ __align__(16) __nv_bfloat16 g_mem_bf16[C_DIM * D_DIM];
__device__ float g_mem_norm[C_DIM];
__device__ __align__(16) float g_part[(size_t)B_DIM * NT * KNN];  // 64 MB partials

// ---------------------------------------------------------------------------
__device__ __forceinline__ uint32_t smem_u32(const void* p) {
    uint32_t a;
    asm("{ .reg .u64 t; cvta.to.shared.u64 t, %1; cvt.u32.u64 %0, t; }" : "=r"(a) : "l"(p));
    return a;
}
__device__ __forceinline__ void ldsm_x4(uint32_t* r, uint32_t addr) {
    asm volatile("ldmatrix.sync.aligned.m8n8.x4.shared.b16 {%0,%1,%2,%3}, [%4];"
                 : "=r"(r[0]), "=r"(r[1]), "=r"(r[2]), "=r"(r[3]) : "r"(addr));
}
__device__ __forceinline__ void cp16(uint32_t dst, const void* src) {
    asm volatile("cp.async.cg.shared.global [%0], [%1], 16;" :: "r"(dst), "l"(src));
}
__device__ __forceinline__ void cp16z(uint32_t dst, const void* src, int srcsize) {
    asm volatile("cp.async.cg.shared.global [%0], [%1], 16, %2;"
                 :: "r"(dst), "l"(src), "r"(srcsize));
}

// ---------------------------------------------------------------------------
// Kernel 1: fused prep. Blocks [0, ENC_BLKS): encoder (2 batch rows per
// block, 256 threads). Blocks [ENC_BLKS, ...): memory -> bf16 + norms
// (one warp per memory row).
// ---------------------------------------------------------------------------
__global__ void prep_kernel(const float* __restrict__ state,
                            const float* __restrict__ W1, const float* __restrict__ b1,
                            const float* __restrict__ W2, const float* __restrict__ b2,
                            const float* __restrict__ memory) {
    const int bid = blockIdx.x;
    if (bid < ENC_BLKS) {
        __shared__ float s_in[2][D_DIM];
        __shared__ float s_h[2][D_DIM];
        __shared__ float s_red[2][D_DIM];
        const int half = threadIdx.x >> 7;
        const int j = threadIdx.x & 127;
        const int b = bid * 2 + half;

        s_in[half][j] = state[b * D_DIM + j];
        __syncthreads();

        float acc = b1[j];
#pragma unroll 8
        for (int k = 0; k < D_DIM; k++) acc = fmaf(s_in[half][k], W1[k * D_DIM + j], acc);
        s_h[half][j] = fmaxf(acc, 0.0f);
        __syncthreads();

        float acc2 = b2[j];
#pragma unroll 8
        for (int k = 0; k < D_DIM; k++) acc2 = fmaf(s_h[half][k], W2[k * D_DIM + j], acc2);

        __nv_bfloat16 q = __float2bfloat16(acc2);
        float qf = __bfloat162float(q);
        g_enc_bf16[b * D_DIM + j] = q;
        s_red[half][j] = qf * qf;
        __syncthreads();
#pragma unroll
        for (int s = 64; s > 0; s >>= 1) {
            if (j < s) s_red[half][j] += s_red[half][j + s];
            __syncthreads();
        }
        if (j == 0) g_enc_norm[b] = s_red[half][0];
    } else {
        const int warp = (bid - ENC_BLKS) * 8 + (threadIdx.x >> 5);
        const int lane = threadIdx.x & 31;
        if (warp >= C_DIM) return;

        const float4 v = ((const float4*)(memory + (size_t)warp * D_DIM))[lane];
        __nv_bfloat16 q0 = __float2bfloat16(v.x);
        __nv_bfloat16 q1 = __float2bfloat16(v.y);
        __nv_bfloat16 q2 = __float2bfloat16(v.z);
        __nv_bfloat16 q3 = __float2bfloat16(v.w);
        float f0 = __bfloat162float(q0), f1 = __bfloat162float(q1);
        float f2 = __bfloat162float(q2), f3 = __bfloat162float(q3);

        __nv_bfloat162* dst = (__nv_bfloat162*)(g_mem_bf16 + (size_t)warp * D_DIM);
        dst[lane * 2 + 0] = __halves2bfloat162(q0, q1);
        dst[lane * 2 + 1] = __halves2bfloat162(q2, q3);

        float sum = f0 * f0 + f1 * f1 + f2 * f2 + f3 * f3;
#pragma unroll
        for (int off = 16; off > 0; off >>= 1)
            sum += __shfl_xor_sync(0xFFFFFFFFu, sum, off);
        if (lane == 0) g_mem_norm[warp] = sum;
    }
}

// ---------------------------------------------------------------------------
__device__ __forceinline__ void topk_insert(float (&top)[KNN], float v) {
    if (v < top[KNN - 1]) {
        top[KNN - 1] = v;
#pragma unroll
        for (int i = KNN - 2; i >= 0; i--) {
            if (top[i + 1] < top[i]) {
                float tmp = top[i]; top[i] = top[i + 1]; top[i + 1] = tmp;
            }
        }
    }
}

// ---------------------------------------------------------------------------
// Kernel 3: distance GEMM (mma.sync bf16) + fused per-tile top-10.
// 128x128x128 tile, 8 warps (4 M x 2 N). K split into two 64-chunks,
// double-buffered cp.async. Epilogue: sq tile -> smem fp32 (repurposed),
// 2 thr/row top-10 with float4 tile reads.
// ---------------------------------------------------------------------------
__global__ void __launch_bounds__(256) dist_gemm_kernel() {
    extern __shared__ __align__(1024) char smem[];
    const uint32_t sA = smem_u32(smem);            // chunk c at sA + c*CH
    const uint32_t sB = sA + 16384;                // chunk c at sB + c*CH
    float* s_tile = (float*)smem;

    const int tid = threadIdx.x;
    const int wid = tid >> 5, lane = tid & 31;
    const int g = lane >> 2, t = lane & 3;
    const int m7 = lane & 7;
    const int wm = wid >> 1, wn = wid & 1;
    const int rowBase = blockIdx.y * TILE;
    const int colBase = blockIdx.x * TILE;

    // ---- stage both K-chunks, one commit group per chunk ----
#pragma unroll
    for (int c = 0; c < 2; c++) {
#pragma unroll
        for (int i = 0; i < 4; i++) {
            int idx = tid + i * 256;               // 1024 16B units
            int row = idx >> 3, s = idx & 7;
            uint32_t dst = sA + c * CH + ((row * 8 + (s ^ (row & 7))) << 4);
            cp16(dst, g_enc_bf16 + (size_t)(rowBase + row) * D_DIM + c * 64 + s * 8);
        }
#pragma unroll
        for (int i = 0; i < 4; i++) {
            int idx = tid + i * 256;
            int row = idx >> 3, s = idx & 7;
            int col = colBase + row;
            int ccol = (col < C_DIM) ? col : (C_DIM - 1);
            uint32_t dst = sB + c * CH + ((row * 8 + (s ^ (row & 7))) << 4);
            cp16z(dst, g_mem_bf16 + (size_t)ccol * D_DIM + c * 64 + s * 8,
                  (col < C_DIM) ? 16 : 0);
        }
        asm volatile("cp.async.commit_group;");
    }

    // ---- fragment lane mapping (per-chunk bases add c*CH) ----
    const int asel = lane >> 4;          // 0/1: k-seg select for A
    const int bsel = (lane >> 3) & 1;    // 0/1: k-seg select for B
    const uint32_t aoff0 = sA + ((wm * 32 + (lane & 15)) << 7);
    const uint32_t aoff1 = aoff0 + (16 << 7);
    uint32_t boff[4];
#pragma unroll
    for (int p = 0; p < 4; p++)
        boff[p] = sB + ((wn * 64 + p * 16 + m7 + ((lane >> 4) & 1) * 8) << 7);

    float acc[2][8][4];
#pragma unroll
    for (int mi = 0; mi < 2; mi++)
#pragma unroll
        for (int nj = 0; nj < 8; nj++)
#pragma unroll
            for (int r = 0; r < 4; r++) acc[mi][nj][r] = 0.0f;

    // ---- pipelined mainloop: chunk0 compute overlaps chunk1 loads ----
#pragma unroll
    for (int c = 0; c < 2; c++) {
        if (c == 0) asm volatile("cp.async.wait_group 1;" ::: "memory");
        else        asm volatile("cp.async.wait_group 0;" ::: "memory");
        __syncthreads();

        const uint32_t co = c * CH;
#pragma unroll
        for (int ks = 0; ks < 4; ks++) {
            const uint32_t sa = (uint32_t)(((2 * ks + asel) ^ m7) << 4);
            const uint32_t sb = (uint32_t)(((2 * ks + bsel) ^ m7) << 4);
            uint32_t a0[4], a1[4];
            ldsm_x4(a0, aoff0 + co + sa);
            ldsm_x4(a1, aoff1 + co + sa);
#pragma unroll
            for (int p = 0; p < 4; p++) {
                uint32_t b[4];
                ldsm_x4(b, boff[p] + co + sb);
#pragma unroll
                for (int h = 0; h < 2; h++) {   // nj = 2p+h
                    asm volatile(
                        "mma.sync.aligned.m16n8k16.row.col.f32.bf16.bf16.f32 "
                        "{%0,%1,%2,%3}, {%4,%5,%6,%7}, {%8,%9}, {%0,%1,%2,%3};\n"
                        : "+f"(acc[0][2 * p + h][0]), "+f"(acc[0][2 * p + h][1]),
                          "+f"(acc[0][2 * p + h][2]), "+f"(acc[0][2 * p + h][3])
                        : "r"(a0[0]), "r"(a0[1]), "r"(a0[2]), "r"(a0[3]),
                          "r"(b[2 * h]), "r"(b[2 * h + 1]));
                    asm volatile(
                        "mma.sync.aligned.m16n8k16.row.col.f32.bf16.bf16.f32 "
                        "{%0,%1,%2,%3}, {%4,%5,%6,%7}, {%8,%9}, {%0,%1,%2,%3};\n"
                        : "+f"(acc[1][2 * p + h][0]), "+f"(acc[1][2 * p + h][1]),
                          "+f"(acc[1][2 * p + h][2]), "+f"(acc[1][2 * p + h][3])
                        : "r"(a1[0]), "r"(a1[1]), "r"(a1[2]), "r"(a1[3]),
                          "r"(b[2 * h]), "r"(b[2 * h + 1]));
                }
            }
        }
    }

    // ---- epilogue: sq tile -> shared fp32 ----
    __syncthreads();   // all smem operand reads done; safe to repurpose
#pragma unroll
    for (int mi = 0; mi < 2; mi++) {
        const int r0 = wm * 32 + mi * 16 + g;
        const float en0 = g_enc_norm[rowBase + r0];
        const float en8 = g_enc_norm[rowBase + r0 + 8];
#pragma unroll
        for (int nj = 0; nj < 8; nj++) {
            const int cl = wn * 64 + nj * 8 + 2 * t;
            const int col = colBase + cl;
            float2 v0, v1;
            if (col < C_DIM) {   // C_DIM even: pair never straddles the edge
                const float mn0 = g_mem_norm[col];
                const float mn1 = g_mem_norm[col + 1];
                v0.x = en0 + mn0 - 2.0f * acc[mi][nj][0];
                v0.y = en0 + mn1 - 2.0f * acc[mi][nj][1];
                v1.x = en8 + mn0 - 2.0f * acc[mi][nj][2];
                v1.y = en8 + mn1 - 2.0f * acc[mi][nj][3];
            } else {
                v0.x = v0.y = v1.x = v1.y = 3.0e38f;
            }
            *(float2*)(s_tile + (size_t)r0 * SPAD + cl) = v0;
            *(float2*)(s_tile + (size_t)(r0 + 8) * SPAD + cl) = v1;
        }
    }
    __syncthreads();

    // ---- per-row top-10: 2 threads/row, 64 cols each (float4 reads) ----
    const int srow = tid >> 1, shalf = tid & 1;
    float top[KNN];
#pragma unroll
    for (int i = 0; i < KNN; i++) top[i] = 3.0e38f;
    const float4* bp4 = (const float4*)(s_tile + (size_t)srow * SPAD + shalf * 64);
#pragma unroll
    for (int j = 0; j < 16; j++) {
        float4 v = bp4[j];
        topk_insert(top, v.x);
        topk_insert(top, v.y);
        topk_insert(top, v.z);
        topk_insert(top, v.w);
    }
    __syncthreads();

    if (shalf) {
#pragma unroll
        for (int i = 0; i < KNN; i++) s_tile[srow * KNN + i] = top[i];
    }
    __syncthreads();
    if (!shalf) {
        const float* q = s_tile + srow * KNN;
#pragma unroll
        for (int i = 0; i < KNN; i++) topk_insert(top, q[i]);
        float* dst = g_part + ((size_t)(rowBase + srow) * NT + blockIdx.x) * KNN;
#pragma unroll
        for (int i = 0; i < KNN; i++) dst[i] = top[i];
    }
}

// ---------------------------------------------------------------------------
// Kernel 4: merge NT per-tile top-10 lists per row (float4 loads).
// NT*KNN = 7820 = 4 * 1955. Flattened merge tree:
// 256 x ~30 -> 64 x 40 -> 8 x 80 -> 1 x 80 inserts.
// ---------------------------------------------------------------------------
__global__ void reduce_topk(float* __restrict__ out) {
    __shared__ float s1[256 * KNN];
    __shared__ float s2[64 * KNN];
    __shared__ float s3[8 * KNN];
    const int row = blockIdx.x;
    const int tid = threadIdx.x;
    const float4* p4 = (const float4*)(g_part + (size_t)row * NT * KNN);

    float top[KNN];
#pragma unroll
    for (int i = 0; i < KNN; i++) top[i] = 3.0e38f;

    for (int c = tid; c < 1955; c += 256) {
        float4 v = p4[c];
        topk_insert(top, v.x);
        topk_insert(top, v.y);
        topk_insert(top, v.z);
        topk_insert(top, v.w);
    }

#pragma unroll
    for (int i = 0; i < KNN; i++) s1[tid * KNN + i] = top[i];
    __syncthreads();

    if (tid < 64) {
        float t2[KNN];
#pragma unroll
        for (int i = 0; i < KNN; i++) t2[i] = 3.0e38f;
        const int base = tid * 4 * KNN;
        for (int c = 0; c < 4 * KNN; c++) topk_insert(t2, s1[base + c]);
#pragma unroll
        for (int i = 0; i < KNN; i++) s2[tid * KNN + i] = t2[i];
    }
    __syncthreads();

    if (tid < 8) {
        float t3[KNN];
#pragma unroll
        for (int i = 0; i < KNN; i++) t3[i] = 3.0e38f;
        const int base = tid * 8 * KNN;
        for (int c = 0; c < 8 * KNN; c++) topk_insert(t3, s2[base + c]);
#pragma unroll
        for (int i = 0; i < KNN; i++) s3[tid * KNN + i] = t3[i];
    }
    __syncthreads();

    if (tid == 0) {
        float t4[KNN];
#pragma unroll
        for (int i = 0; i < KNN; i++) t4[i] = 3.0e38f;
        for (int c = 0; c < 8 * KNN; c++) topk_insert(t4, s3[c]);
        float sum = 0.0f;
#pragma unroll
        for (int i = 0; i < KNN; i++) sum += sqrtf(fmaxf(t4[i], 1e-12f));
        out[row] = sum * (1.0f / KNN);
    }
}

// ---------------------------------------------------------------------------
#define SMEM_SZ (TILE * SPAD * 4)   /* 67584 >= 65536 operand bytes */

extern "C" void kernel_launch(void* const* d_in, const int* in_sizes, int n_in,
                              void* d_out, int out_size) {
    const float* state  = (const float*)d_in[0];
    const float* W1     = (const float*)d_in[1];
    const float* b1     = (const float*)d_in[2];
    const float* W2     = (const float*)d_in[3];
    const float* b2     = (const float*)d_in[4];
    const float* memory = (const float*)d_in[5];

    cudaFuncSetAttribute(dist_gemm_kernel,
                         cudaFuncAttributeMaxDynamicSharedMemorySize, SMEM_SZ);

    prep_kernel<<<ENC_BLKS + MEM_BLKS, 256>>>(state, W1, b1, W2, b2, memory);

    dim3 grid(NT, MT);
    dist_gemm_kernel<<<grid, 256, SMEM_SZ>>>();

    reduce_topk<<<B_DIM, 256>>>((float*)d_out);
}